// round 7
// baseline (speedup 1.0000x reference)
#include <cuda_runtime.h>
#include <cuda_bf16.h>

#define N_NODES 100000
#define D 32
#define ELL_W 64   // max in-degree; deg ~ Poisson(16), P(>=64) ~ 1e-17 per node

// ------------------------- scratch (__device__ globals) --------------------
__device__ float g_agg[N_NODES * D];        // aggregated mean features
__device__ float g_h1[N_NODES * D];         // layer-1 output
__device__ int   g_cnt[N_NODES];            // per-node fill cursor == in-degree
__device__ int   g_ell[N_NODES * ELL_W];    // ELL src-index table

// ---------------------------------------------------------------------------
// Edge-parallel ELL fill: slot = cursor++, write src index into dst row.
__global__ void ell_fill_kernel(const int* __restrict__ src,
                                const int* __restrict__ dst,
                                int* __restrict__ cnt,
                                int* __restrict__ ell, int E) {
    int e = blockIdx.x * blockDim.x + threadIdx.x;
    if (e >= E) return;
    int d = dst[e];
    int slot = atomicAdd(&cnt[d], 1);
    if (slot < ELL_W) ell[d * ELL_W + slot] = src[e];
}

// ---------------------------------------------------------------------------
// Gather-mean: warp per node. 4 edges per LDG.128, lane = (egrp, cgrp).
// All 8 chunk indices are shfl-broadcast FIRST (independent), then all 8
// predicated LDG.128s issue back-to-back -> MLP ~8 hides the L2 hit latency.
__global__ void gather_kernel(const float* __restrict__ x,
                              const int* __restrict__ cnt,
                              const int* __restrict__ ell,
                              float* __restrict__ agg, int n) {
    int gw = (blockIdx.x * blockDim.x + threadIdx.x) >> 5;
    int lane = threadIdx.x & 31;
    if (gw >= n) return;

    int deg = cnt[gw];
    int m = deg < ELL_W ? deg : ELL_W;
    const int* row = ell + gw * ELL_W;

    // coalesced index preload: lanes cover slots [0,32) and [32,64)
    int s_lo = (lane < m) ? row[lane] : 0;

    int egrp = lane >> 3;   // 0..3 : which edge within a 4-edge chunk
    int cgrp = lane & 7;    // 0..7 : which float4 column group

    // Broadcast all 8 chunk indices up-front (independent SHFLs).
    int idx[8];
#pragma unroll
    for (int c = 0; c < 8; c++)
        idx[c] = __shfl_sync(0xffffffffu, s_lo, c * 4 + egrp);

    int mlo = m < 32 ? m : 32;
    float4 acc = make_float4(0.0f, 0.0f, 0.0f, 0.0f);
#pragma unroll
    for (int c = 0; c < 8; c++) {
        if (c * 4 + egrp < mlo) {
            float4 v = *reinterpret_cast<const float4*>(
                x + (size_t)idx[c] * D + cgrp * 4);
            acc.x += v.x; acc.y += v.y; acc.z += v.z; acc.w += v.w;
        }
    }

    if (m > 32) {   // rare: deg > 32
        int s_hi = (lane + 32 < m) ? row[lane + 32] : 0;
        int idh[8];
#pragma unroll
        for (int c = 0; c < 8; c++)
            idh[c] = __shfl_sync(0xffffffffu, s_hi, c * 4 + egrp);
#pragma unroll
        for (int c = 0; c < 8; c++) {
            if (32 + c * 4 + egrp < m) {
                float4 v = *reinterpret_cast<const float4*>(
                    x + (size_t)idh[c] * D + cgrp * 4);
                acc.x += v.x; acc.y += v.y; acc.z += v.z; acc.w += v.w;
            }
        }
    }

    // reduce across the 4 edge subgroups (lanes differing in bits 3,4)
#pragma unroll
    for (int off = 8; off <= 16; off <<= 1) {
        acc.x += __shfl_xor_sync(0xffffffffu, acc.x, off);
        acc.y += __shfl_xor_sync(0xffffffffu, acc.y, off);
        acc.z += __shfl_xor_sync(0xffffffffu, acc.z, off);
        acc.w += __shfl_xor_sync(0xffffffffu, acc.w, off);
    }

    float inv = 1.0f / fmaxf((float)deg, 1.0f);
    if (lane < 8) {
        float4 o = make_float4(acc.x * inv, acc.y * inv, acc.z * inv, acc.w * inv);
        *reinterpret_cast<float4*>(agg + (size_t)gw * D + lane * 4) = o;
    }
}

// ---------------------------------------------------------------------------
// Transform (proven R3 version): out[n] = relu( agg[n] @ Wl + b + root[n] @ Wr )
__global__ void transform_kernel(const float* __restrict__ agg,
                                 const float* __restrict__ root,
                                 const float* __restrict__ Wl,
                                 const float* __restrict__ Wr,
                                 const float* __restrict__ b,
                                 float* __restrict__ out, int n) {
    int lane = threadIdx.x & 31;
    int w = blockIdx.x * (blockDim.x >> 5) + (threadIdx.x >> 5);
    int nWarps = gridDim.x * (blockDim.x >> 5);

    float wl[D], wr[D];
#pragma unroll
    for (int k = 0; k < D; k++) {
        wl[k] = Wl[k * D + lane];
        wr[k] = Wr[k * D + lane];
    }
    float bias = b[lane];

    for (int node = w; node < n; node += nWarps) {
        const float4* ap = reinterpret_cast<const float4*>(agg + (size_t)node * D);
        const float4* rp = reinterpret_cast<const float4*>(root + (size_t)node * D);
        float accA = 0.0f, accR = 0.0f;
#pragma unroll
        for (int k0 = 0; k0 < D / 4; k0++) {
            float4 a = ap[k0];   // uniform address -> broadcast LDG.128
            float4 r = rp[k0];
            accA = fmaf(a.x, wl[4 * k0 + 0], accA);
            accA = fmaf(a.y, wl[4 * k0 + 1], accA);
            accA = fmaf(a.z, wl[4 * k0 + 2], accA);
            accA = fmaf(a.w, wl[4 * k0 + 3], accA);
            accR = fmaf(r.x, wr[4 * k0 + 0], accR);
            accR = fmaf(r.y, wr[4 * k0 + 1], accR);
            accR = fmaf(r.z, wr[4 * k0 + 2], accR);
            accR = fmaf(r.w, wr[4 * k0 + 3], accR);
        }
        float o = accA + bias + accR;
        out[(size_t)node * D + lane] = fmaxf(o, 0.0f);
    }
}

// ---------------------------------------------------------------------------
extern "C" void kernel_launch(void* const* d_in, const int* in_sizes, int n_in,
                              void* d_out, int out_size) {
    const float* x = (const float*)d_in[0];
    const int* edge_index = (const int*)d_in[1];   // int32 (JAX x64 disabled)
    const float* W1l = (const float*)d_in[2];
    const float* W1r = (const float*)d_in[3];
    const float* b1  = (const float*)d_in[4];
    const float* W2l = (const float*)d_in[5];
    const float* W2r = (const float*)d_in[6];
    const float* b2  = (const float*)d_in[7];
    float* out = (float*)d_out;

    const int E = in_sizes[1] / 2;
    const int N = N_NODES;
    const int* src = edge_index;
    const int* dst = edge_index + E;

    float* agg; cudaGetSymbolAddress((void**)&agg, g_agg);
    float* h1;  cudaGetSymbolAddress((void**)&h1, g_h1);
    int* cnt;   cudaGetSymbolAddress((void**)&cnt, g_cnt);
    int* ell;   cudaGetSymbolAddress((void**)&ell, g_ell);

    const int TPB = 256;
    const int nb_edges = (E + TPB - 1) / TPB;           // 6250
    const int nb_gather = (N * 32 + TPB - 1) / TPB;     // 12500 (warp/node)
    const int nb_xform = 1184;                          // 8 blocks/SM grid-stride

    // ---- ELL build (reused by both layers) ----
    cudaMemsetAsync(cnt, 0, N * sizeof(int));
    ell_fill_kernel<<<nb_edges, TPB>>>(src, dst, cnt, ell, E);

    // ---- Layer 1 ----
    gather_kernel<<<nb_gather, TPB>>>(x, cnt, ell, agg, N);
    transform_kernel<<<nb_xform, TPB>>>(agg, x, W1l, W1r, b1, h1, N);

    // ---- Layer 2 ----
    gather_kernel<<<nb_gather, TPB>>>(h1, cnt, ell, agg, N);
    transform_kernel<<<nb_xform, TPB>>>(agg, h1, W2l, W2r, b2, out, N);
}

// round 8
// speedup vs baseline: 1.0538x; 1.0538x over previous
#include <cuda_runtime.h>
#include <cuda_bf16.h>

#define N_NODES 100000
#define D 32
#define ELL_W 64   // max in-degree; deg ~ Poisson(16), P(>=64) ~ 1e-17 per node

// ------------------------- scratch (__device__ globals) --------------------
__device__ float g_agg[N_NODES * D];        // aggregated mean features
__device__ float g_h1[N_NODES * D];         // layer-1 output
__device__ int   g_cnt[N_NODES];            // per-node fill cursor == in-degree
__device__ int   g_ell[N_NODES * ELL_W];    // ELL src-index table

// ---------------------------------------------------------------------------
// Edge-parallel ELL fill: slot = cursor++, write src index into dst row.
__global__ void ell_fill_kernel(const int* __restrict__ src,
                                const int* __restrict__ dst,
                                int* __restrict__ cnt,
                                int* __restrict__ ell, int E) {
    int e = blockIdx.x * blockDim.x + threadIdx.x;
    if (e >= E) return;
    int d = dst[e];
    int slot = atomicAdd(&cnt[d], 1);
    if (slot < ELL_W) ell[d * ELL_W + slot] = src[e];
}

// ---------------------------------------------------------------------------
// Gather-mean: TWO nodes per warp; two independent dependency chains overlap.
// lane = (egrp = lane>>3, cgrp = lane&7). Per node, 8 chunk indices are read
// directly per-lane from ELL (no shfl in critical path), then 8 predicated
// LDG.128s accumulate float4s. Butterfly-reduce over egrp; lanes 0-15 store
// both contiguous 128B output rows with one coalesced float4 store.
__global__ void gather_kernel(const float* __restrict__ x,
                              const int* __restrict__ cnt,
                              const int* __restrict__ ell,
                              float* __restrict__ agg, int n) {
    int gw = (blockIdx.x * blockDim.x + threadIdx.x) >> 5;
    int lane = threadIdx.x & 31;
    int node0 = gw * 2;
    int node1 = node0 + 1;
    if (node0 >= n) return;
    bool has1 = (node1 < n);

    int egrp = lane >> 3;   // 0..3 : edge within a 4-edge chunk
    int cgrp = lane & 7;    // 0..7 : float4 column group

    // Independent front-end loads for both nodes.
    int deg0 = cnt[node0];
    int deg1 = has1 ? cnt[node1] : 0;
    int m0 = deg0 < ELL_W ? deg0 : ELL_W;
    int m1 = deg1 < ELL_W ? deg1 : ELL_W;
    const int* row0 = ell + node0 * ELL_W;
    const int* row1 = ell + node1 * ELL_W;

    // Direct index loads: 8 per node, all independent. Lanes sharing egrp+c
    // read the same address (hardware broadcast within the 128B line).
    int id0[8], id1[8];
#pragma unroll
    for (int c = 0; c < 8; c++) {
        int e = c * 4 + egrp;
        id0[c] = (e < m0) ? row0[e] : -1;
        id1[c] = (has1 && e < m1) ? row1[e] : -1;
    }

    float4 acc0 = make_float4(0.f, 0.f, 0.f, 0.f);
    float4 acc1 = make_float4(0.f, 0.f, 0.f, 0.f);
#pragma unroll
    for (int c = 0; c < 8; c++) {
        if (id0[c] >= 0) {
            float4 v = *reinterpret_cast<const float4*>(
                x + (size_t)id0[c] * D + cgrp * 4);
            acc0.x += v.x; acc0.y += v.y; acc0.z += v.z; acc0.w += v.w;
        }
        if (id1[c] >= 0) {
            float4 v = *reinterpret_cast<const float4*>(
                x + (size_t)id1[c] * D + cgrp * 4);
            acc1.x += v.x; acc1.y += v.y; acc1.z += v.z; acc1.w += v.w;
        }
    }

    // Rare tail: deg > 32 (slots 32..63), handled with the same structure.
    if (m0 > 32 || m1 > 32) {
#pragma unroll
        for (int c = 0; c < 8; c++) {
            int e = 32 + c * 4 + egrp;
            if (e < m0) {
                float4 v = *reinterpret_cast<const float4*>(
                    x + (size_t)row0[e] * D + cgrp * 4);
                acc0.x += v.x; acc0.y += v.y; acc0.z += v.z; acc0.w += v.w;
            }
            if (has1 && e < m1) {
                float4 v = *reinterpret_cast<const float4*>(
                    x + (size_t)row1[e] * D + cgrp * 4);
                acc1.x += v.x; acc1.y += v.y; acc1.z += v.z; acc1.w += v.w;
            }
        }
    }

    // Reduce across the 4 edge subgroups (lanes differing in bits 3,4).
#pragma unroll
    for (int off = 8; off <= 16; off <<= 1) {
        acc0.x += __shfl_xor_sync(0xffffffffu, acc0.x, off);
        acc0.y += __shfl_xor_sync(0xffffffffu, acc0.y, off);
        acc0.z += __shfl_xor_sync(0xffffffffu, acc0.z, off);
        acc0.w += __shfl_xor_sync(0xffffffffu, acc0.w, off);
        acc1.x += __shfl_xor_sync(0xffffffffu, acc1.x, off);
        acc1.y += __shfl_xor_sync(0xffffffffu, acc1.y, off);
        acc1.z += __shfl_xor_sync(0xffffffffu, acc1.z, off);
        acc1.w += __shfl_xor_sync(0xffffffffu, acc1.w, off);
    }

    float inv0 = 1.0f / fmaxf((float)deg0, 1.0f);
    float inv1 = 1.0f / fmaxf((float)deg1, 1.0f);

    // Lanes 0-7 store node0's row, lanes 8-15 store node1's row (contiguous).
    if (lane < 8) {
        float4 o = make_float4(acc0.x * inv0, acc0.y * inv0,
                               acc0.z * inv0, acc0.w * inv0);
        *reinterpret_cast<float4*>(agg + (size_t)node0 * D + cgrp * 4) = o;
    } else if (lane < 16 && has1) {
        float4 o = make_float4(acc1.x * inv1, acc1.y * inv1,
                               acc1.z * inv1, acc1.w * inv1);
        *reinterpret_cast<float4*>(agg + (size_t)node1 * D + cgrp * 4) = o;
    }
}

// ---------------------------------------------------------------------------
// Transform (proven R3 version): out[n] = relu( agg[n] @ Wl + b + root[n] @ Wr )
__global__ void transform_kernel(const float* __restrict__ agg,
                                 const float* __restrict__ root,
                                 const float* __restrict__ Wl,
                                 const float* __restrict__ Wr,
                                 const float* __restrict__ b,
                                 float* __restrict__ out, int n) {
    int lane = threadIdx.x & 31;
    int w = blockIdx.x * (blockDim.x >> 5) + (threadIdx.x >> 5);
    int nWarps = gridDim.x * (blockDim.x >> 5);

    float wl[D], wr[D];
#pragma unroll
    for (int k = 0; k < D; k++) {
        wl[k] = Wl[k * D + lane];
        wr[k] = Wr[k * D + lane];
    }
    float bias = b[lane];

    for (int node = w; node < n; node += nWarps) {
        const float4* ap = reinterpret_cast<const float4*>(agg + (size_t)node * D);
        const float4* rp = reinterpret_cast<const float4*>(root + (size_t)node * D);
        float accA = 0.0f, accR = 0.0f;
#pragma unroll
        for (int k0 = 0; k0 < D / 4; k0++) {
            float4 a = ap[k0];   // uniform address -> broadcast LDG.128
            float4 r = rp[k0];
            accA = fmaf(a.x, wl[4 * k0 + 0], accA);
            accA = fmaf(a.y, wl[4 * k0 + 1], accA);
            accA = fmaf(a.z, wl[4 * k0 + 2], accA);
            accA = fmaf(a.w, wl[4 * k0 + 3], accA);
            accR = fmaf(r.x, wr[4 * k0 + 0], accR);
            accR = fmaf(r.y, wr[4 * k0 + 1], accR);
            accR = fmaf(r.z, wr[4 * k0 + 2], accR);
            accR = fmaf(r.w, wr[4 * k0 + 3], accR);
        }
        float o = accA + bias + accR;
        out[(size_t)node * D + lane] = fmaxf(o, 0.0f);
    }
}

// ---------------------------------------------------------------------------
extern "C" void kernel_launch(void* const* d_in, const int* in_sizes, int n_in,
                              void* d_out, int out_size) {
    const float* x = (const float*)d_in[0];
    const int* edge_index = (const int*)d_in[1];   // int32 (JAX x64 disabled)
    const float* W1l = (const float*)d_in[2];
    const float* W1r = (const float*)d_in[3];
    const float* b1  = (const float*)d_in[4];
    const float* W2l = (const float*)d_in[5];
    const float* W2r = (const float*)d_in[6];
    const float* b2  = (const float*)d_in[7];
    float* out = (float*)d_out;

    const int E = in_sizes[1] / 2;
    const int N = N_NODES;
    const int* src = edge_index;
    const int* dst = edge_index + E;

    float* agg; cudaGetSymbolAddress((void**)&agg, g_agg);
    float* h1;  cudaGetSymbolAddress((void**)&h1, g_h1);
    int* cnt;   cudaGetSymbolAddress((void**)&cnt, g_cnt);
    int* ell;   cudaGetSymbolAddress((void**)&ell, g_ell);

    const int TPB = 256;
    const int nb_edges = (E + TPB - 1) / TPB;              // 6250
    const int nWarpsG = (N + 1) / 2;                       // 2 nodes per warp
    const int nb_gather = (nWarpsG * 32 + TPB - 1) / TPB;  // 6250
    const int nb_xform = 600;                              // grid-stride (proven)

    // ---- ELL build (reused by both layers) ----
    cudaMemsetAsync(cnt, 0, N * sizeof(int));
    ell_fill_kernel<<<nb_edges, TPB>>>(src, dst, cnt, ell, E);

    // ---- Layer 1 ----
    gather_kernel<<<nb_gather, TPB>>>(x, cnt, ell, agg, N);
    transform_kernel<<<nb_xform, TPB>>>(agg, x, W1l, W1r, b1, h1, N);

    // ---- Layer 2 ----
    gather_kernel<<<nb_gather, TPB>>>(h1, cnt, ell, agg, N);
    transform_kernel<<<nb_xform, TPB>>>(agg, h1, W2l, W2r, b2, out, N);
}